// round 5
// baseline (speedup 1.0000x reference)
#include <cuda_runtime.h>
#include <math.h>

#define N_NODES 8000
#define T_DIM   12
#define NT      (N_NODES * T_DIM)      // 96000

#define NODES_PER_BLK 64
#define NTHREADS      480
#define NBLOCKS       (N_NODES / NODES_PER_BLK)   // 125  (<=148 SMs: all co-resident)

// Row-per-block partials. Rows 125..127 are never written -> stay 0.0 (static
// zero-init), so each combine quarter sums exactly 32 rows in fixed order.
__device__ float    g_part[128][128];
__device__ unsigned g_arrive;          // monotonic epoch counter (never reset)

__global__ void __launch_bounds__(NTHREADS)
fused_kernel(const float* __restrict__ x,
             const float* __restrict__ U1,
             const float* __restrict__ U2,   // (5, 8000) row-major
             const float* __restrict__ U3,
             const float* __restrict__ be,
             const float* __restrict__ Ve,
             const float* __restrict__ w,    // conv2_w (5,5,1,3) flat o*15+i*3+k
             const float* __restrict__ bias, // conv2_b (5,)
             float* __restrict__ out)
{
    __shared__ float sX [NODES_PER_BLK][61];      // x[nl][t*5+f], pad 61 (odd)
    __shared__ float sRhs[NODES_PER_BLK][13];     // rhs[nl][t] = sum_f x*U3
    __shared__ float sX2[5][NODES_PER_BLK * 13];  // x2[f][nl*13+t]
    __shared__ float sQ[4][120];                  // combine quarters
    __shared__ float sU1[NODES_PER_BLK];
    __shared__ float sU2[5][NODES_PER_BLK];
    __shared__ float sU3[5];
    __shared__ float sLhs[60];
    __shared__ float sM2[60];
    __shared__ float sAt[12][12];
    __shared__ float sW[75];
    __shared__ float sB[5];

    const int tid = threadIdx.x;
    const int b   = blockIdx.x;
    const int n0  = b * NODES_PER_BLK;

    // ---- Coalesced load of this block's 64x60 floats (960 float4, 2 rounds) ----
    {
        const float4* xp = (const float4*)(x + n0 * 60);
        #pragma unroll
        for (int r = 0; r < 2; r++) {
            const int j = tid + r * NTHREADS;     // 0..959
            float4 v = xp[j];
            const int n = j / 15;
            const int c = (j % 15) * 4;
            float* d = &sX[n][c];
            d[0] = v.x; d[1] = v.y; d[2] = v.z; d[3] = v.w;
        }
    }
    // small parameter tiles (independent loads, overlap with x in-flight)
    if (tid < NODES_PER_BLK) sU1[tid] = U1[n0 + tid];
    if (tid < 320) {
        const int f2 = tid / NODES_PER_BLK, nl = tid % NODES_PER_BLK;
        sU2[f2][nl] = U2[f2 * N_NODES + n0 + nl];
    }
    if (tid < 5)  sU3[tid] = U3[tid];
    if (tid < 75) sW[tid] = w[tid];
    if (tid >= 96 && tid < 101) sB[tid - 96] = bias[tid - 96];
    __syncthreads();

    // ---- rhs[nl][t] = sum_f sX[nl][t*5+f] * U3[f]  (768 entries, 480 threads) ----
    for (int j = tid; j < NODES_PER_BLK * 12; j += NTHREADS) {
        const int nl = j / 12, t = j % 12;
        float r = 0.f;
        #pragma unroll
        for (int f = 0; f < 5; f++) r += sX[nl][t * 5 + f] * sU3[f];
        sRhs[nl][t] = r;
    }
    __syncthreads();

    // ---- This block's partials over its 64 nodes ----
    //   j<60   : lhs_p[t*5+f]   = sum_nl sX[nl][j] * U1[nl]
    //   60..119: M2_p[f2*12+t]  = sum_nl U2[f2][nl] * rhs[nl][t]
    if (tid < 120) {
        float acc = 0.f;
        if (tid < 60) {
            #pragma unroll 8
            for (int nl = 0; nl < NODES_PER_BLK; nl++)
                acc += sX[nl][tid] * sU1[nl];
        } else {
            const int jj = tid - 60;
            const int f2 = jj / 12, t = jj % 12;
            #pragma unroll 8
            for (int nl = 0; nl < NODES_PER_BLK; nl++)
                acc += sU2[f2][nl] * sRhs[nl][t];
        }
        g_part[b][tid] = acc;        // 120 consecutive floats: coalesced
    }
    __syncthreads();                  // orders all STGs before tid0's fence

    // ---- Grid barrier: single release fence + monotonic epoch counter ----
    if (tid == 0) {
        __threadfence();                              // release (one MEMBAR.GPU)
        unsigned old = atomicAdd(&g_arrive, 1u);
        unsigned target = (old / (unsigned)NBLOCKS + 1u) * (unsigned)NBLOCKS;
        volatile unsigned* va = &g_arrive;
        while (*va < target) { }
        __threadfence();                              // acquire
    }
    __syncthreads();

    // ---- Combine partials: (quarter q, j) sums 32 rows, warp-coalesced ----
    {
        const int q = tid / 120;      // 0..3
        const int j = tid % 120;
        const float* p = &g_part[q * 32][0];
        float s = 0.f;
        #pragma unroll
        for (int i = 0; i < 32; i++)
            s += __ldcg(p + i * 128 + j);             // rows 125..127 read as 0
        sQ[q][j] = s;
    }
    __syncthreads();
    if (tid < 120) {
        float s = sQ[0][tid] + sQ[1][tid] + sQ[2][tid] + sQ[3][tid];
        if (tid < 60) sLhs[tid] = s;
        else          sM2[tid - 60] = s;
    }
    __syncthreads();

    // ---- At2 column-wise in warp 0 (lane t2 owns a column; no block syncs) ----
    if (tid < 12) {
        const int t2 = tid;
        float S[12];
        #pragma unroll
        for (int t1 = 0; t1 < 12; t1++) {
            float p = 0.f;
            #pragma unroll
            for (int f = 0; f < 5; f++) p += sLhs[t1 * 5 + f] * sM2[f * 12 + t2];
            p += be[t1 * 12 + t2];
            S[t1] = 1.f / (1.f + expf(-p));
        }
        float E[12];
        #pragma unroll
        for (int t1 = 0; t1 < 12; t1++) {
            float e = 0.f;
            #pragma unroll
            for (int k = 0; k < 12; k++) e += Ve[t1 * 12 + k] * S[k];  // lane-uniform
            E[t1] = e;
        }
        float mx = -1e30f;
        #pragma unroll
        for (int k = 0; k < 12; k++) mx = fmaxf(mx, E[k]);
        float den = 0.f;
        #pragma unroll
        for (int k = 0; k < 12; k++) { E[k] = expf(E[k] - mx); den += E[k]; }
        const float inv = 1.f / den;
        #pragma unroll
        for (int k = 0; k < 12; k++) sAt[k][t2] = E[k] * inv;
    }
    __syncthreads();

    // ---- Phase B: thread (f, nl) computes x2[f][nl][0..11] ----
    if (tid < 320) {
        const int f  = tid / NODES_PER_BLK;
        const int nl = tid % NODES_PER_BLK;
        float xr[12];
        #pragma unroll
        for (int tp = 0; tp < 12; tp++) xr[tp] = sX[nl][tp * 5 + f];
        float* dst = &sX2[f][nl * 13];
        #pragma unroll
        for (int t = 0; t < 12; t++) {
            float a = 0.f;
            #pragma unroll
            for (int tp = 0; tp < 12; tp++) a += xr[tp] * sAt[tp][t];
            dst[t] = a;
        }
    }
    __syncthreads();

    // ---- Phase C: thread (o, nl) conv plane + coalesced 48B store ----
    if (tid < 320) {
        const int o  = tid / NODES_PER_BLK;
        const int nl = tid % NODES_PER_BLK;
        float wr[15];
        #pragma unroll
        for (int i = 0; i < 15; i++) wr[i] = sW[o * 15 + i];
        const float b0 = sB[o];

        float yr[12];
        #pragma unroll
        for (int t = 0; t < 12; t++) yr[t] = b0;
        #pragma unroll
        for (int fi = 0; fi < 5; fi++) {
            const float* s = &sX2[fi][nl * 13];
            float v[12];
            #pragma unroll
            for (int t = 0; t < 12; t++) v[t] = s[t];
            const float w0 = wr[fi * 3 + 0], w1 = wr[fi * 3 + 1], w2 = wr[fi * 3 + 2];
            #pragma unroll
            for (int t = 0; t < 12; t++) {
                float a = w1 * v[t];
                if (t > 0)  a += w0 * v[t - 1];
                if (t < 11) a += w2 * v[t + 1];
                yr[t] += a;
            }
        }
        // raw-reshape output: flat = o*N*T + n*T + t
        float4* op = (float4*)(out + o * NT + (n0 + nl) * 12);
        op[0] = make_float4(yr[0], yr[1], yr[2],  yr[3]);
        op[1] = make_float4(yr[4], yr[5], yr[6],  yr[7]);
        op[2] = make_float4(yr[8], yr[9], yr[10], yr[11]);
    }
}

extern "C" void kernel_launch(void* const* d_in, const int* in_sizes, int n_in,
                              void* d_out, int out_size)
{
    // metadata order: x, adj, U1_1, U2_1, U3_1, be_1, Ve_1,
    //                 U1_2, U2_2, U3_2, be_2, Ve_2,
    //                 conv1_w, conv1_b, conv2_w, conv2_b, W_hgc, b_hgc
    const float* x    = (const float*)d_in[0];
    const float* U1_2 = (const float*)d_in[7];
    const float* U2_2 = (const float*)d_in[8];
    const float* U3_2 = (const float*)d_in[9];
    const float* be_2 = (const float*)d_in[10];
    const float* Ve_2 = (const float*)d_in[11];
    const float* c2w  = (const float*)d_in[14];
    const float* c2b  = (const float*)d_in[15];
    float* out = (float*)d_out;

    // Hyperbolic branch contributes exactly 0.0*finite -> skipped entirely.
    fused_kernel<<<NBLOCKS, NTHREADS>>>(x, U1_2, U2_2, U3_2, be_2, Ve_2, c2w, c2b, out);
}

// round 7
// speedup vs baseline: 1.0152x; 1.0152x over previous
#include <cuda_runtime.h>
#include <math.h>

#define N_NODES 8000
#define NT      (N_NODES * 12)        // 96000

#define NODES_PER_BLK 64
#define NMAIN   125                   // main blocks (8000/64)
#define NTHREADS 320
#define NBLOCKS (NMAIN + 1)           // +1 At2 block; 126 <= 148 SMs -> co-resident

// Row-per-block partials: g_part[b][j], rows 125..127 never written (stay 0.0
// from static zero-init) -> combine sums a fixed 64 rows per half, deterministic.
__device__ float    g_part[128][128];
__device__ float    gAt2[144];         // At2[t1*12+t2], written once per replay
__device__ unsigned g_arrive;          // += NMAIN per replay (monotonic)
__device__ unsigned g_obs;             // += 1 per replay (At2 block's epoch)
__device__ unsigned g_ready;           // += 1 per replay (At2 published)

__global__ void __launch_bounds__(NTHREADS)
fused_kernel(const float* __restrict__ x,
             const float* __restrict__ U1,
             const float* __restrict__ U2,   // (5, 8000) row-major
             const float* __restrict__ U3,
             const float* __restrict__ be,
             const float* __restrict__ Ve,
             const float* __restrict__ w,    // conv2_w (5,5,1,3) flat o*15+i*3+k
             const float* __restrict__ bias, // conv2_b (5,)
             float* __restrict__ out)
{
    const int tid = threadIdx.x;
    const int b   = blockIdx.x;

    // ======================= At2 block (block 125) =======================
    if (b == NMAIN) {
        __shared__ float sQ[2][120];
        __shared__ float sLhs[60];
        __shared__ float sM2[60];
        __shared__ unsigned sEpoch;

        if (tid == 0) sEpoch = atomicAdd(&g_obs, 1u);   // exact replay index
        __syncthreads();
        const unsigned e = sEpoch;

        if (tid == 0) {
            volatile unsigned* va = &g_arrive;
            const unsigned target = (e + 1u) * (unsigned)NMAIN;
            while (*va < target) { }
            __threadfence();                            // acquire
        }
        __syncthreads();

        // Combine 125 partial rows (+3 zero rows): half q sums rows q*64..q*64+63,
        // coalesced across j within each row.
        if (tid < 240) {
            const int q = tid / 120, j = tid % 120;
            const float* p = &g_part[q * 64][0];
            float s = 0.f;
            #pragma unroll 16
            for (int i = 0; i < 64; i++)
                s += __ldcg(p + i * 128 + j);
            sQ[q][j] = s;
        }
        __syncthreads();
        if (tid < 120) {
            float s = sQ[0][tid] + sQ[1][tid];
            if (tid < 60) sLhs[tid] = s;
            else          sM2[tid - 60] = s;
        }
        __syncthreads();

        // At2 column-wise in warp 0: lane t2 owns a column
        if (tid < 12) {
            const int t2 = tid;
            float S[12];
            #pragma unroll
            for (int t1 = 0; t1 < 12; t1++) {
                float p = 0.f;
                #pragma unroll
                for (int f = 0; f < 5; f++) p += sLhs[t1 * 5 + f] * sM2[f * 12 + t2];
                p += be[t1 * 12 + t2];
                S[t1] = 1.f / (1.f + expf(-p));
            }
            float E[12];
            #pragma unroll
            for (int t1 = 0; t1 < 12; t1++) {
                float ee = 0.f;
                #pragma unroll
                for (int k = 0; k < 12; k++) ee += Ve[t1 * 12 + k] * S[k];  // lane-uniform
                E[t1] = ee;
            }
            float mx = -1e30f;
            #pragma unroll
            for (int k = 0; k < 12; k++) mx = fmaxf(mx, E[k]);
            float den = 0.f;
            #pragma unroll
            for (int k = 0; k < 12; k++) { E[k] = expf(E[k] - mx); den += E[k]; }
            const float inv = 1.f / den;
            #pragma unroll
            for (int k = 0; k < 12; k++) gAt2[k * 12 + t2] = E[k] * inv;
        }
        __syncthreads();                 // all 12 lanes' STGs done
        if (tid == 0) {
            __threadfence();             // release gAt2
            atomicAdd(&g_ready, 1u);     // becomes e+1
        }
        return;
    }

    // ========================= main blocks (0..124) =========================
    __shared__ float sX [NODES_PER_BLK][61];      // x[nl][t*5+f], pad 61
    __shared__ float sRhs[NODES_PER_BLK][13];     // rhs[nl][t]
    __shared__ float sX2[5][NODES_PER_BLK * 13];  // x2[f][nl*13+t]
    __shared__ float sU1[NODES_PER_BLK];
    __shared__ float sU2[5][NODES_PER_BLK];
    __shared__ float sU3[5];
    __shared__ float sAt[12][12];
    __shared__ float sW[75];
    __shared__ float sB[5];
    __shared__ unsigned sEp;

    const int n0 = b * NODES_PER_BLK;

    // ---- Coalesced x-tile load: 960 float4, 3 rounds of 320 ----
    {
        const float4* xp = (const float4*)(x + n0 * 60);
        #pragma unroll
        for (int r = 0; r < 3; r++) {
            const int j = tid + r * NTHREADS;
            float4 v = xp[j];
            const int n = j / 15;
            const int c = (j % 15) * 4;
            float* d = &sX[n][c];
            d[0] = v.x; d[1] = v.y; d[2] = v.z; d[3] = v.w;
        }
    }
    if (tid < NODES_PER_BLK) sU1[tid] = U1[n0 + tid];
    if (tid < 5)  sU3[tid] = U3[tid];
    {
        const int f2 = tid / NODES_PER_BLK, nl = tid % NODES_PER_BLK;   // covers all 320
        sU2[f2][nl] = U2[f2 * N_NODES + n0 + nl];
    }
    if (tid >= 64 && tid < 139)  sW[tid - 64]  = w[tid - 64];
    if (tid >= 160 && tid < 165) sB[tid - 160] = bias[tid - 160];
    __syncthreads();

    // ---- rhs[nl][t] = sum_f x * U3 ----
    for (int j = tid; j < NODES_PER_BLK * 12; j += NTHREADS) {
        const int nl = j / 12, t = j % 12;
        float r = 0.f;
        #pragma unroll
        for (int f = 0; f < 5; f++) r += sX[nl][t * 5 + f] * sU3[f];
        sRhs[nl][t] = r;
    }
    __syncthreads();

    // ---- This block's 120 partials over its 64 nodes ----
    if (tid < 120) {
        float acc = 0.f;
        if (tid < 60) {
            #pragma unroll 8
            for (int nl = 0; nl < NODES_PER_BLK; nl++)
                acc += sX[nl][tid] * sU1[nl];
        } else {
            const int jj = tid - 60;
            const int f2 = jj / 12, t = jj % 12;
            #pragma unroll 8
            for (int nl = 0; nl < NODES_PER_BLK; nl++)
                acc += sU2[f2][nl] * sRhs[nl][t];
        }
        g_part[b][tid] = acc;            // coalesced 120-float row
    }
    __syncthreads();                     // order STGs before release fence

    // ---- Publish + wait for At2 (single fence, monotonic epochs) ----
    if (tid == 0) {
        __threadfence();                                  // release partials
        unsigned old = atomicAdd(&g_arrive, 1u);
        sEp = old / (unsigned)NMAIN;                      // this replay's epoch
        volatile unsigned* vr = &g_ready;
        const unsigned target = sEp + 1u;
        while (*vr < target) { }
        __threadfence();                                  // acquire gAt2
    }
    __syncthreads();

    if (tid < 144) sAt[tid / 12][tid % 12] = __ldcg(&gAt2[tid]);
    __syncthreads();

    // ---- Phase B: thread (f, nl) computes x2[f][nl][0..11] ----
    {
        const int f  = tid / NODES_PER_BLK;
        const int nl = tid % NODES_PER_BLK;
        float xr[12];
        #pragma unroll
        for (int tp = 0; tp < 12; tp++) xr[tp] = sX[nl][tp * 5 + f];
        float* dst = &sX2[f][nl * 13];
        #pragma unroll
        for (int t = 0; t < 12; t++) {
            float a = 0.f;
            #pragma unroll
            for (int tp = 0; tp < 12; tp++) a += xr[tp] * sAt[tp][t];
            dst[t] = a;
        }
    }
    __syncthreads();

    // ---- Phase C: thread (o, nl) conv plane + coalesced 48B store ----
    {
        const int o  = tid / NODES_PER_BLK;
        const int nl = tid % NODES_PER_BLK;
        float wr[15];
        #pragma unroll
        for (int i = 0; i < 15; i++) wr[i] = sW[o * 15 + i];
        const float b0 = sB[o];

        float yr[12];
        #pragma unroll
        for (int t = 0; t < 12; t++) yr[t] = b0;
        #pragma unroll
        for (int fi = 0; fi < 5; fi++) {
            const float* s = &sX2[fi][nl * 13];
            float v[12];
            #pragma unroll
            for (int t = 0; t < 12; t++) v[t] = s[t];
            const float w0 = wr[fi * 3 + 0], w1 = wr[fi * 3 + 1], w2 = wr[fi * 3 + 2];
            #pragma unroll
            for (int t = 0; t < 12; t++) {
                float a = w1 * v[t];
                if (t > 0)  a += w0 * v[t - 1];
                if (t < 11) a += w2 * v[t + 1];
                yr[t] += a;
            }
        }
        // raw-reshape output: flat = o*N*T + n*T + t
        float4* op = (float4*)(out + o * NT + (n0 + nl) * 12);
        op[0] = make_float4(yr[0], yr[1], yr[2],  yr[3]);
        op[1] = make_float4(yr[4], yr[5], yr[6],  yr[7]);
        op[2] = make_float4(yr[8], yr[9], yr[10], yr[11]);
    }
}

extern "C" void kernel_launch(void* const* d_in, const int* in_sizes, int n_in,
                              void* d_out, int out_size)
{
    // metadata order: x, adj, U1_1, U2_1, U3_1, be_1, Ve_1,
    //                 U1_2, U2_2, U3_2, be_2, Ve_2,
    //                 conv1_w, conv1_b, conv2_w, conv2_b, W_hgc, b_hgc
    const float* x    = (const float*)d_in[0];
    const float* U1_2 = (const float*)d_in[7];
    const float* U2_2 = (const float*)d_in[8];
    const float* U3_2 = (const float*)d_in[9];
    const float* be_2 = (const float*)d_in[10];
    const float* Ve_2 = (const float*)d_in[11];
    const float* c2w  = (const float*)d_in[14];
    const float* c2b  = (const float*)d_in[15];
    float* out = (float*)d_out;

    // Hyperbolic branch contributes exactly 0.0*finite -> skipped entirely.
    fused_kernel<<<NBLOCKS, NTHREADS>>>(x, U1_2, U2_2, U3_2, be_2, Ve_2, c2w, c2b, out);
}